// round 1
// baseline (speedup 1.0000x reference)
#include <cuda_runtime.h>
#include <cuda_bf16.h>

// out[v,:] = coef * sum_k ( 2*x[v,:]*x[nbr[v,k],:] + x[nbr[v,k],:]^2 )
//          = coef * ( 2*x[v,:]*S1 + S2 ),  S1 = sum_k xu, S2 = sum_k xu^2
// N=100000, K=16, D=128, coef = (2/6)/16 = 1/48.
// One warp per node; each lane owns a float4 (D=128 = 32 lanes * 4 floats).

#define TMP_K 16
#define TMP_D4 32   // D/4 float4s per row

__global__ __launch_bounds__(256) void TMessagePassing_11974368821731_kernel(
    const float4* __restrict__ x,      // [N, 32] float4
    const int*    __restrict__ nbr,    // [N, 16]
    float4*       __restrict__ out,    // [N, 32] float4
    int n)
{
    int warp = (int)((blockIdx.x * blockDim.x + threadIdx.x) >> 5);
    int lane = threadIdx.x & 31;
    if (warp >= n) return;

    const float coef  = 1.0f / 48.0f;
    const float coef2 = 2.0f / 48.0f;

    // Preload all 16 neighbor indices (uniform across warp -> broadcast, L1-hit).
    const int* nv = nbr + warp * TMP_K;
    int idx[TMP_K];
#pragma unroll
    for (int k = 0; k < TMP_K; k++) idx[k] = __ldg(&nv[k]);

    // 16 independent gathers, fully unrolled for MLP ~16.
    float4 s1 = make_float4(0.f, 0.f, 0.f, 0.f);
    float4 s2 = make_float4(0.f, 0.f, 0.f, 0.f);
#pragma unroll
    for (int k = 0; k < TMP_K; k++) {
        float4 u = __ldg(&x[(long long)idx[k] * TMP_D4 + lane]);
        s1.x += u.x; s1.y += u.y; s1.z += u.z; s1.w += u.w;
        s2.x = fmaf(u.x, u.x, s2.x);
        s2.y = fmaf(u.y, u.y, s2.y);
        s2.z = fmaf(u.z, u.z, s2.z);
        s2.w = fmaf(u.w, u.w, s2.w);
    }

    float4 xv = __ldg(&x[(long long)warp * TMP_D4 + lane]);
    float4 o;
    o.x = fmaf(coef2 * xv.x, s1.x, coef * s2.x);
    o.y = fmaf(coef2 * xv.y, s1.y, coef * s2.y);
    o.z = fmaf(coef2 * xv.z, s1.z, coef * s2.z);
    o.w = fmaf(coef2 * xv.w, s1.w, coef * s2.w);
    out[(long long)warp * TMP_D4 + lane] = o;
}

extern "C" void kernel_launch(void* const* d_in, const int* in_sizes, int n_in,
                              void* d_out, int out_size)
{
    const float4* x   = (const float4*)d_in[0];
    const int*    nbr = (const int*)d_in[1];
    float4*       out = (float4*)d_out;

    int n = in_sizes[1] / TMP_K;           // N nodes (nbr has N*K elements)

    int warps_per_block = 256 / 32;        // 8 warps -> 8 nodes per block
    int blocks = (n + warps_per_block - 1) / warps_per_block;
    TMessagePassing_11974368821731_kernel<<<blocks, 256>>>(x, nbr, out, n);
}

// round 3
// speedup vs baseline: 1.0091x; 1.0091x over previous
#include <cuda_runtime.h>
#include <cuda_bf16.h>

// out[v,:] = coef * ( 2*x[v,:]*S1 + S2 ),  S1 = sum_k x[nbr[v,k]], S2 = sum_k x[nbr[v,k]]^2
// N=100000, K=16, D=128, coef = (2/6)/16 = 1/48.
// One warp per node; each lane owns a float4 (D=128 = 32 lanes * 4 floats).
// Identical to the 49.9us R1 kernel except the out store is streaming
// (evict-first) so the output stream does not evict x from L2 across replays.

#define TMP_K 16
#define TMP_D4 32   // D/4 float4s per row

__global__ __launch_bounds__(256) void TMessagePassing_11974368821731_kernel(
    const float4* __restrict__ x,      // [N, 32] float4
    const int*    __restrict__ nbr,    // [N, 16]
    float4*       __restrict__ out,    // [N, 32] float4
    int n)
{
    int warp = (int)((blockIdx.x * blockDim.x + threadIdx.x) >> 5);
    int lane = threadIdx.x & 31;
    if (warp >= n) return;

    const float coef  = 1.0f / 48.0f;
    const float coef2 = 2.0f / 48.0f;

    // Preload all 16 neighbor indices (uniform across warp -> broadcast, L1-hit).
    const int* nv = nbr + warp * TMP_K;
    int idx[TMP_K];
#pragma unroll
    for (int k = 0; k < TMP_K; k++) idx[k] = __ldg(&nv[k]);

    // 16 independent gathers, fully unrolled for MLP ~16.
    float4 s1 = make_float4(0.f, 0.f, 0.f, 0.f);
    float4 s2 = make_float4(0.f, 0.f, 0.f, 0.f);
#pragma unroll
    for (int k = 0; k < TMP_K; k++) {
        float4 u = __ldg(&x[(long long)idx[k] * TMP_D4 + lane]);
        s1.x += u.x; s1.y += u.y; s1.z += u.z; s1.w += u.w;
        s2.x = fmaf(u.x, u.x, s2.x);
        s2.y = fmaf(u.y, u.y, s2.y);
        s2.z = fmaf(u.z, u.z, s2.z);
        s2.w = fmaf(u.w, u.w, s2.w);
    }

    float4 xv = __ldg(&x[(long long)warp * TMP_D4 + lane]);
    float4 o;
    o.x = fmaf(coef2 * xv.x, s1.x, coef * s2.x);
    o.y = fmaf(coef2 * xv.y, s1.y, coef * s2.y);
    o.z = fmaf(coef2 * xv.z, s1.z, coef * s2.z);
    o.w = fmaf(coef2 * xv.w, s1.w, coef * s2.w);

    // Streaming store: evict-first so out writes don't evict x from L2.
    __stcs(&out[(long long)warp * TMP_D4 + lane], o);
}

extern "C" void kernel_launch(void* const* d_in, const int* in_sizes, int n_in,
                              void* d_out, int out_size)
{
    const float4* x   = (const float4*)d_in[0];
    const int*    nbr = (const int*)d_in[1];
    float4*       out = (float4*)d_out;

    int n = in_sizes[1] / TMP_K;           // N nodes (nbr has N*K elements)

    int warps_per_block = 256 / 32;        // 8 warps -> 8 nodes per block
    int blocks = (n + warps_per_block - 1) / warps_per_block;
    TMessagePassing_11974368821731_kernel<<<blocks, 256>>>(x, nbr, out, n);
}

// round 4
// speedup vs baseline: 1.0428x; 1.0335x over previous
#include <cuda_runtime.h>
#include <cuda_bf16.h>

// out[v,:] = coef * ( 2*x[v,:]*S1 + S2 ),  S1 = sum_k x[nbr[v,k]], S2 = sum_k x[nbr[v,k]]^2
// N=100000, K=16, D=128, coef = (2/6)/16 = 1/48.
// One warp per node. Loads are float2 (LDG.64, 2 lines/request) instead of
// float4 (4 lines/request): same total wavefronts, but spread across 2x the
// LDG instructions so L1tex services them at the ~1.0 cyc/wf cross-LDG rate
// rather than the 2.07 cyc/wf within-LDG replay rate.
// Lane L owns elements {2L, 2L+1} (first half-row) and {64+2L, 65+2L} (second).

#define TMP_K 16

__global__ __launch_bounds__(256) void TMessagePassing_11974368821731_kernel(
    const float2* __restrict__ x,      // [N, 64] float2
    const int*    __restrict__ nbr,    // [N, 16]
    float2*       __restrict__ out,    // [N, 64] float2
    int n)
{
    int warp = (int)((blockIdx.x * blockDim.x + threadIdx.x) >> 5);
    int lane = threadIdx.x & 31;
    if (warp >= n) return;

    const float coef  = 1.0f / 48.0f;
    const float coef2 = 2.0f / 48.0f;

    // Preload all 16 neighbor indices (uniform across warp -> broadcast).
    const int* nv = nbr + warp * TMP_K;
    int idx[TMP_K];
#pragma unroll
    for (int k = 0; k < TMP_K; k++) idx[k] = __ldg(&nv[k]);

    // Self row (2 half-rows), issued early.
    const long long vbase = (long long)warp * 64;
    float2 xva = __ldg(&x[vbase + lane]);
    float2 xvb = __ldg(&x[vbase + 32 + lane]);

    float2 s1a = make_float2(0.f, 0.f), s2a = make_float2(0.f, 0.f);
    float2 s1b = make_float2(0.f, 0.f), s2b = make_float2(0.f, 0.f);

    // 32 independent LDG.64 gathers, fully unrolled.
#pragma unroll
    for (int k = 0; k < TMP_K; k++) {
        const long long ubase = (long long)idx[k] * 64;
        float2 ua = __ldg(&x[ubase + lane]);
        float2 ub = __ldg(&x[ubase + 32 + lane]);
        s1a.x += ua.x; s1a.y += ua.y;
        s1b.x += ub.x; s1b.y += ub.y;
        s2a.x = fmaf(ua.x, ua.x, s2a.x);
        s2a.y = fmaf(ua.y, ua.y, s2a.y);
        s2b.x = fmaf(ub.x, ub.x, s2b.x);
        s2b.y = fmaf(ub.y, ub.y, s2b.y);
    }

    float2 oa, ob;
    oa.x = fmaf(coef2 * xva.x, s1a.x, coef * s2a.x);
    oa.y = fmaf(coef2 * xva.y, s1a.y, coef * s2a.y);
    ob.x = fmaf(coef2 * xvb.x, s1b.x, coef * s2b.x);
    ob.y = fmaf(coef2 * xvb.y, s1b.y, coef * s2b.y);

    // Streaming stores: keep out from evicting x in L2.
    __stcs(&out[vbase + lane], oa);
    __stcs(&out[vbase + 32 + lane], ob);
}

extern "C" void kernel_launch(void* const* d_in, const int* in_sizes, int n_in,
                              void* d_out, int out_size)
{
    const float2* x   = (const float2*)d_in[0];
    const int*    nbr = (const int*)d_in[1];
    float2*       out = (float2*)d_out;

    int n = in_sizes[1] / TMP_K;           // N nodes (nbr has N*K elements)

    int warps_per_block = 256 / 32;        // 8 warps -> 8 nodes per block
    int blocks = (n + warps_per_block - 1) / warps_per_block;
    TMessagePassing_11974368821731_kernel<<<blocks, 256>>>(x, nbr, out, n);
}